// round 13
// baseline (speedup 1.0000x reference)
#include <cuda_runtime.h>

// VectorNormSelection, round 13: R12 + FSETP compares on the FMA pipe.
// Identical algorithm/semantics to R12 (packed u32 key (norm&~63)|(63-idx),
// exactness detector, exact u64 slow path). Change: in every
// direction-carrying compare-exchange, the compare is done as a FLOAT
// compare of the key bits (__uint_as_float). Keys are nonneg finite floats
// (norm exponent < 0xFF, sign 0), so float order == unsigned bit order:
// bit-identical results. FSETP issues on the (otherwise ~empty) FMA pipe,
// relieving the saturated ALU pipe (R12: alu=81.7% of pipe ceiling);
// selects stay integer SELP. Unconditional maxes (halving) and fixed-
// direction local stages keep single IMNMX (already 1 alu op).

#define WPB 8          // warps per block
#define RPW 4          // rows per warp
#define FULLM 0xffffffffu

typedef unsigned u32;
typedef unsigned long long u64;

// float-domain strict compare of nonneg-float key bits (FSETP, fma pipe)
__device__ __forceinline__ bool fgt(u32 a, u32 b) {
    return __uint_as_float(a) > __uint_as_float(b);
}

// ---------- packed u32 stages ----------
template <int JH>
__device__ __forceinline__ void pstage_x(u32& e0, u32& e1, bool takeMax) {
    u32 p0 = __shfl_xor_sync(FULLM, e0, JH);
    u32 p1 = __shfl_xor_sync(FULLM, e1, JH);
    bool w0 = (fgt(p0, e0) == takeMax);    // FSETP(fma) + PLOP(alu)
    bool w1 = (fgt(p1, e1) == takeMax);
    e0 = w0 ? p0 : e0;                     // SELP(alu)
    e1 = w1 ? p1 : e1;
}
// local stage, lane-varying direction
__device__ __forceinline__ void pstage_l(u32& e0, u32& e1, bool descR) {
    bool w = (fgt(e0, e1) == descR);       // keep as-is iff matches direction
    u32 a0 = w ? e0 : e1;
    u32 a1 = w ? e1 : e0;
    e0 = a0; e1 = a1;
}
// local stage, fixed descending: 2 IMNMX, optimal
__device__ __forceinline__ void pstage_lT(u32& e0, u32& e1) {
    u32 hi = max(e0, e1), lo = min(e0, e1);
    e0 = hi; e1 = lo;
}
// bitonic halving: unconditional max, 1 IMNMX per element
template <int XM>
__device__ __forceinline__ void phalve_x(u32& e0, u32& e1) {
    u32 p0 = __shfl_xor_sync(FULLM, e0, XM);
    u32 p1 = __shfl_xor_sync(FULLM, e1, XM);
    e0 = max(e0, p1);
    e1 = max(e1, p0);
}

// ---------- exact u64 stages (slow path; R7-validated) ----------
__device__ __forceinline__ u64 cexg(u64 e, u64 p, bool takeMax) {
    return ((p > e) == takeMax) ? p : e;
}
template <int JH>
__device__ __forceinline__ void kstage_x(u64& e0, u64& e1, bool takeMax) {
    u64 p0 = __shfl_xor_sync(FULLM, e0, JH);
    u64 p1 = __shfl_xor_sync(FULLM, e1, JH);
    e0 = cexg(e0, p0, takeMax);
    e1 = cexg(e1, p1, takeMax);
}
__device__ __forceinline__ void kstage_l(u64& e0, u64& e1, bool descR) {
    bool gt = e0 > e1;
    u64 hi = gt ? e0 : e1;
    u64 lo = gt ? e1 : e0;
    e0 = descR ? hi : lo;
    e1 = descR ? lo : hi;
}
template <int XM>
__device__ __forceinline__ void khalve_x(u64& e0, u64& e1) {
    u64 p0 = __shfl_xor_sync(FULLM, e0, XM);
    u64 p1 = __shfl_xor_sync(FULLM, e1, XM);
    e0 = (p1 > e0) ? p1 : e0;
    e1 = (p0 > e1) ? p0 : e1;
}

__global__ void __launch_bounds__(WPB * 32)
vecnorm_topk_kernel(const float* __restrict__ x, float* __restrict__ out, int nrows)
{
    const int lane = threadIdx.x & 31;
    const int wg   = blockIdx.x * WPB + (threadIdx.x >> 5);
    const int rowBase = wg * RPW;
    if (rowBase >= nrows) return;
    const int rowsHere = min(RPW, nrows - rowBase);

    // hoisted direction predicates (row-independent; R10-validated wiring)
    const bool d2 = ((lane & 1) == 0);
    const bool d4 = ((lane & 2) == 0);
    const bool d8 = ((lane & 4) == 0);
    const bool x1_d4 = (d2 == d4);
    const bool x2_d8 = (((lane & 2) == 0) == d8);
    const bool x1_d8 = (d2 == d8);
    const bool x4_T  = ((lane & 4) == 0);
    const bool x2_T  = ((lane & 2) == 0);
    const bool x1_T  = d2;

    // gather routing constants
    const int f2 = 32 + lane;
    const int j1 = lane / 3, c1 = lane - 3 * j1;
    const int j2 = f2 / 3,   c2 = f2 - 3 * j2;

    const u32 tag0 = (u32)(63 - 2 * lane);
    const u32 tag1 = (u32)(62 - 2 * lane);

    const float* xr   = x   + (size_t)rowBase * 192;
    float*       outr = out + (size_t)rowBase * 48;

#pragma unroll 1
    for (int i = 0; i < rowsHere; i++) {
        // ---- load 6 floats (vectors 2*lane, 2*lane+1), coalesced ----
        const float2* xr2 = reinterpret_cast<const float2*>(xr);
        float2 a = xr2[3 * lane + 0];
        float2 b = xr2[3 * lane + 1];
        float2 c = xr2[3 * lane + 2];
        float n0 = fmaf(a.x, a.x, fmaf(a.y, a.y, b.x * b.x));
        float n1 = fmaf(b.y, b.y, fmaf(c.x, c.x, c.y * c.y));
        u32 w0 = __float_as_uint(n0);
        u32 w1 = __float_as_uint(n1);

        // ---- fast path: packed-key bitonic network ----
        u32 k0 = (w0 & 0xFFFFFFC0u) | tag0;
        u32 k1 = (w1 & 0xFFFFFFC0u) | tag1;

        pstage_l(k0, k1, d2);                // k=2  j=1
        pstage_x<1>(k0, k1, x1_d4);          // k=4  j=2
        pstage_l(k0, k1, d4);                //      j=1
        pstage_x<2>(k0, k1, x2_d8);          // k=8  j=4
        pstage_x<1>(k0, k1, x1_d8);          //      j=2
        pstage_l(k0, k1, d8);                //      j=1
        pstage_x<4>(k0, k1, x4_T);           // k=16 j=8
        pstage_x<2>(k0, k1, x2_T);           //      j=4
        pstage_x<1>(k0, k1, x1_T);           //      j=2
        pstage_lT(k0, k1);                   //      j=1 (desc)

        phalve_x<15>(k0, k1);                // merge A
        pstage_x<4>(k0, k1, x4_T);
        pstage_x<2>(k0, k1, x2_T);
        pstage_x<1>(k0, k1, x1_T);
        pstage_lT(k0, k1);

        phalve_x<23>(k0, k1);                // merge B -> top-16 in lanes 0-7
        pstage_x<4>(k0, k1, x4_T);
        pstage_x<2>(k0, k1, x2_T);
        pstage_x<1>(k0, k1, x1_T);
        pstage_lT(k0, k1);

        // ---- exactness detector (warp-uniform) ----
        u32 v0t = k0 >> 6, v1t = k1 >> 6;               // high-26 value fields
        u32 nv0 = __shfl_down_sync(FULLM, v0t, 1);
        bool adj = (lane < 8 && v0t == v1t) || (lane < 7 && v1t == nv0);
        u32 t26 = __shfl_sync(FULLM, v1t, 7);           // rank-15 high-26
        int tot = __popc(__ballot_sync(FULLM, (w0 >> 6) == t26)) +
                  __popc(__ballot_sync(FULLM, (w1 >> 6) == t26));
        bool slow = __any_sync(FULLM, adj) || (tot >= 2);

        unsigned idx0, idx1;
        if (!slow) {
            idx0 = 63u - (k0 & 63u);
            idx1 = 63u - (k1 & 63u);
        } else {
            // ---- slow path: exact u64 network (R7-validated) ----
            u64 e0 = ((u64)w0 << 32) | (u64)tag0;
            u64 e1 = ((u64)w1 << 32) | (u64)tag1;
            kstage_l(e0, e1, d2);
            kstage_x<1>(e0, e1, x1_d4);
            kstage_l(e0, e1, d4);
            kstage_x<2>(e0, e1, x2_d8);
            kstage_x<1>(e0, e1, x1_d8);
            kstage_l(e0, e1, d8);
            kstage_x<4>(e0, e1, x4_T);
            kstage_x<2>(e0, e1, x2_T);
            kstage_x<1>(e0, e1, x1_T);
            kstage_l(e0, e1, true);
            khalve_x<15>(e0, e1);
            kstage_x<4>(e0, e1, x4_T);
            kstage_x<2>(e0, e1, x2_T);
            kstage_x<1>(e0, e1, x1_T);
            kstage_l(e0, e1, true);
            khalve_x<23>(e0, e1);
            kstage_x<4>(e0, e1, x4_T);
            kstage_x<2>(e0, e1, x2_T);
            kstage_x<1>(e0, e1, x1_T);
            kstage_l(e0, e1, true);
            idx0 = 63u - (unsigned)(e0 & 63ull);
            idx1 = 63u - (unsigned)(e1 & 63ull);
        }

        // ---- shared epilogue: broadcast indices, gather (L1-hot), store ----
        unsigned pk = idx0 | (idx1 << 8);
        unsigned pkA = __shfl_sync(FULLM, pk, j1 >> 1);
        unsigned iA  = (j1 & 1) ? ((pkA >> 8) & 0xffu) : (pkA & 0xffu);
        unsigned pkB = __shfl_sync(FULLM, pk, j2 >> 1);
        unsigned iB  = (j2 & 1) ? ((pkB >> 8) & 0xffu) : (pkB & 0xffu);

        outr[lane] = xr[(int)iA * 3 + c1];
        if (lane < 16)
            outr[32 + lane] = xr[(int)iB * 3 + c2];

        xr   += 192;
        outr += 48;
    }
}

extern "C" void kernel_launch(void* const* d_in, const int* in_sizes, int n_in,
                              void* d_out, int out_size)
{
    const float* x   = (const float*)d_in[0];
    float*       out = (float*)d_out;
    int nrows = in_sizes[0] / 192;
    int rowsPerBlock = WPB * RPW;
    int grid = (nrows + rowsPerBlock - 1) / rowsPerBlock;
    vecnorm_topk_kernel<<<grid, WPB * 32>>>(x, out, nrows);
}

// round 14
// speedup vs baseline: 1.2016x; 1.2016x over previous
#include <cuda_runtime.h>

// VectorNormSelection, round 14: R12 + two-row interleaved merge phases.
// Per row pair (A, B):
//   - packed u32 keys (norm&~63)|(63-idx), R12-validated
//   - sort-16 phase run separately per row (all 64 slots live each)
//   - halve<15> per row; lanes 8-15/24-31 then carry row B's (mirrored,
//     still-bitonic) survivors inside row A's registers -> ONE shared clean
//     cascade sorts lanes 0-7/16-23 = row A and 8-15/24-31 = row B
//   - shared halve<23> merges (0-7 vs 16-23)=A and (8-15 vs 24-31)=B with
//     the same instructions; one shared final clean
//   - result: row A top-16 sorted in lanes 0-7, row B in lanes 8-15
// Exactness detector per row (R12-validated conditions); rare rows rerun
// the exact u64 network (R7-validated). Gather epilogue per row.

#define WPB 8          // warps per block
#define RPW 4          // rows per warp (processed in pairs)
#define FULLM 0xffffffffu

typedef unsigned u32;
typedef unsigned long long u64;

// ---------- packed u32 stages (R12 primitives) ----------
template <int JH>
__device__ __forceinline__ void pstage_x(u32& e0, u32& e1, bool takeMax) {
    u32 p0 = __shfl_xor_sync(FULLM, e0, JH);
    u32 p1 = __shfl_xor_sync(FULLM, e1, JH);
    e0 = takeMax ? max(e0, p0) : min(e0, p0);
    e1 = takeMax ? max(e1, p1) : min(e1, p1);
}
__device__ __forceinline__ void pstage_l(u32& e0, u32& e1, bool descR) {
    u32 hi = max(e0, e1), lo = min(e0, e1);
    e0 = descR ? hi : lo;
    e1 = descR ? lo : hi;
}
__device__ __forceinline__ void pstage_lT(u32& e0, u32& e1) {
    u32 hi = max(e0, e1), lo = min(e0, e1);
    e0 = hi; e1 = lo;
}
template <int XM>
__device__ __forceinline__ void phalve_x(u32& e0, u32& e1) {
    u32 p0 = __shfl_xor_sync(FULLM, e0, XM);
    u32 p1 = __shfl_xor_sync(FULLM, e1, XM);
    e0 = max(e0, p1);
    e1 = max(e1, p0);
}

struct Dirs {
    bool d2, d4, d8, x1_d4, x2_d8, x1_d8, x4_T, x2_T, x1_T;
};

__device__ __forceinline__ void psort16(u32& k0, u32& k1, const Dirs& D) {
    pstage_l(k0, k1, D.d2);          // k=2  j=1
    pstage_x<1>(k0, k1, D.x1_d4);    // k=4  j=2
    pstage_l(k0, k1, D.d4);          //      j=1
    pstage_x<2>(k0, k1, D.x2_d8);    // k=8  j=4
    pstage_x<1>(k0, k1, D.x1_d8);    //      j=2
    pstage_l(k0, k1, D.d8);          //      j=1
    pstage_x<4>(k0, k1, D.x4_T);     // k=16 j=8
    pstage_x<2>(k0, k1, D.x2_T);     //      j=4
    pstage_x<1>(k0, k1, D.x1_T);     //      j=2
    pstage_lT(k0, k1);               //      j=1 (desc)
}
__device__ __forceinline__ void pclean(u32& k0, u32& k1, const Dirs& D) {
    pstage_x<4>(k0, k1, D.x4_T);
    pstage_x<2>(k0, k1, D.x2_T);
    pstage_x<1>(k0, k1, D.x1_T);
    pstage_lT(k0, k1);
}

// ---------- exact u64 network (slow path; R7-validated); returns pk, valid lanes 0-7
__device__ __forceinline__ u64 cexg(u64 e, u64 p, bool takeMax) {
    return ((p > e) == takeMax) ? p : e;
}
template <int JH>
__device__ __forceinline__ void kstage_x(u64& e0, u64& e1, bool takeMax) {
    u64 p0 = __shfl_xor_sync(FULLM, e0, JH);
    u64 p1 = __shfl_xor_sync(FULLM, e1, JH);
    e0 = cexg(e0, p0, takeMax);
    e1 = cexg(e1, p1, takeMax);
}
__device__ __forceinline__ void kstage_l(u64& e0, u64& e1, bool descR) {
    bool gt = e0 > e1;
    u64 hi = gt ? e0 : e1;
    u64 lo = gt ? e1 : e0;
    e0 = descR ? hi : lo;
    e1 = descR ? lo : hi;
}
template <int XM>
__device__ __forceinline__ void khalve_x(u64& e0, u64& e1) {
    u64 p0 = __shfl_xor_sync(FULLM, e0, XM);
    u64 p1 = __shfl_xor_sync(FULLM, e1, XM);
    e0 = (p1 > e0) ? p1 : e0;
    e1 = (p0 > e1) ? p0 : e1;
}
__device__ __noinline__ unsigned kexact(u32 w0, u32 w1, u32 tag0, u32 tag1, const Dirs& D) {
    u64 e0 = ((u64)w0 << 32) | (u64)tag0;
    u64 e1 = ((u64)w1 << 32) | (u64)tag1;
    kstage_l(e0, e1, D.d2);
    kstage_x<1>(e0, e1, D.x1_d4);
    kstage_l(e0, e1, D.d4);
    kstage_x<2>(e0, e1, D.x2_d8);
    kstage_x<1>(e0, e1, D.x1_d8);
    kstage_l(e0, e1, D.d8);
    kstage_x<4>(e0, e1, D.x4_T);
    kstage_x<2>(e0, e1, D.x2_T);
    kstage_x<1>(e0, e1, D.x1_T);
    kstage_l(e0, e1, true);
    khalve_x<15>(e0, e1);
    kstage_x<4>(e0, e1, D.x4_T);
    kstage_x<2>(e0, e1, D.x2_T);
    kstage_x<1>(e0, e1, D.x1_T);
    kstage_l(e0, e1, true);
    khalve_x<23>(e0, e1);
    kstage_x<4>(e0, e1, D.x4_T);
    kstage_x<2>(e0, e1, D.x2_T);
    kstage_x<1>(e0, e1, D.x1_T);
    kstage_l(e0, e1, true);
    unsigned idx0 = 63u - (unsigned)(e0 & 63ull);
    unsigned idx1 = 63u - (unsigned)(e1 & 63ull);
    return idx0 | (idx1 << 8);
}

__global__ void __launch_bounds__(WPB * 32)
vecnorm_topk_kernel(const float* __restrict__ x, float* __restrict__ out, int nrows)
{
    const int lane = threadIdx.x & 31;
    const int wg   = blockIdx.x * WPB + (threadIdx.x >> 5);
    const int rowBase = wg * RPW;
    if (rowBase >= nrows) return;
    const int rowsHere = min(RPW, nrows - rowBase);

    Dirs D;
    D.d2 = ((lane & 1) == 0);
    D.d4 = ((lane & 2) == 0);
    D.d8 = ((lane & 4) == 0);
    D.x1_d4 = (D.d2 == D.d4);
    D.x2_d8 = (D.d4 == D.d8);
    D.x1_d8 = (D.d2 == D.d8);
    D.x4_T  = D.d8;
    D.x2_T  = D.d4;
    D.x1_T  = D.d2;

    // gather routing constants
    const int f2 = 32 + lane;
    const int j1 = lane / 3, c1 = lane - 3 * j1;
    const int j2 = f2 / 3,   c2 = f2 - 3 * j2;

    const u32 tag0 = (u32)(63 - 2 * lane);
    const u32 tag1 = (u32)(62 - 2 * lane);

#pragma unroll 1
    for (int i = 0; i < rowsHere; i += 2) {
        const int rowA = rowBase + i;
        const bool hasB = (i + 1) < rowsHere;
        const float* xA = x + (size_t)rowA * 192;
        const float* xB = hasB ? (xA + 192) : xA;

        // ---- load + norms for both rows ----
        const float2* a2 = reinterpret_cast<const float2*>(xA);
        float2 aa = a2[3 * lane + 0];
        float2 ab = a2[3 * lane + 1];
        float2 ac = a2[3 * lane + 2];
        float nA0 = fmaf(aa.x, aa.x, fmaf(aa.y, aa.y, ab.x * ab.x));
        float nA1 = fmaf(ab.y, ab.y, fmaf(ac.x, ac.x, ac.y * ac.y));
        const float2* b2 = reinterpret_cast<const float2*>(xB);
        float2 ba = b2[3 * lane + 0];
        float2 bb = b2[3 * lane + 1];
        float2 bc = b2[3 * lane + 2];
        float nB0 = fmaf(ba.x, ba.x, fmaf(ba.y, ba.y, bb.x * bb.x));
        float nB1 = fmaf(bb.y, bb.y, fmaf(bc.x, bc.x, bc.y * bc.y));

        u32 wA0 = __float_as_uint(nA0), wA1 = __float_as_uint(nA1);
        u32 wB0 = __float_as_uint(nB0), wB1 = __float_as_uint(nB1);

        // ---- packed keys + per-row sort-16 phase ----
        u32 kA0 = (wA0 & 0xFFFFFFC0u) | tag0;
        u32 kA1 = (wA1 & 0xFFFFFFC0u) | tag1;
        u32 kB0 = (wB0 & 0xFFFFFFC0u) | tag0;
        u32 kB1 = (wB1 & 0xFFFFFFC0u) | tag1;
        psort16(kA0, kA1, D);
        psort16(kB0, kB1, D);

        // ---- per-row halvings; upper halves adopt row B's mirrored tops ----
        phalve_x<15>(kA0, kA1);
        phalve_x<15>(kB0, kB1);
        if (lane & 8) { kA0 = kB0; kA1 = kB1; }   // lanes 8-15 & 24-31 carry B

        // ---- shared merge-A clean, shared merge B ----
        pclean(kA0, kA1, D);        // 0-7:A(g01) 8-15:B(g01) 16-23:A(g23) 24-31:B(g23)
        phalve_x<23>(kA0, kA1);     // A: 0-7 vs 16-23 ; B: 8-15 vs 24-31
        pclean(kA0, kA1, D);        // A top16 sorted in lanes 0-7; B in 8-15

        // ---- exactness detector, per row ----
        u32 v0t = kA0 >> 6, v1t = kA1 >> 6;
        u32 nv0 = __shfl_down_sync(FULLM, v0t, 1);
        bool adj = (lane < 16) && ((v0t == v1t) || (((lane & 7) < 7) && (v1t == nv0)));
        u32 adjm = __ballot_sync(FULLM, adj);
        u32 t26A = __shfl_sync(FULLM, v1t, 7);
        u32 t26B = __shfl_sync(FULLM, v1t, 15);
        int totA = __popc(__ballot_sync(FULLM, (wA0 >> 6) == t26A)) +
                   __popc(__ballot_sync(FULLM, (wA1 >> 6) == t26A));
        int totB = __popc(__ballot_sync(FULLM, (wB0 >> 6) == t26B)) +
                   __popc(__ballot_sync(FULLM, (wB1 >> 6) == t26B));
        bool slowA = ((adjm & 0x00FFu) != 0) || (totA >= 2);
        bool slowB = hasB && (((adjm & 0xFF00u) != 0) || (totB >= 2));

        // ---- per-lane pk (A valid in lanes 0-7, B in lanes 8-15) ----
        unsigned pk = (63u - (kA0 & 63u)) | ((63u - (kA1 & 63u)) << 8);
        if (slowA) {
            unsigned pkx = kexact(wA0, wA1, tag0, tag1, D);
            if (lane < 8) pk = pkx;
        }
        if (slowB) {
            unsigned pkx = kexact(wB0, wB1, tag0, tag1, D);
            unsigned up = __shfl_sync(FULLM, pkx, lane & 7);
            if (lane >= 8 && lane < 16) pk = up;
        }

        // ---- epilogue row A ----
        {
            unsigned pA = __shfl_sync(FULLM, pk, j1 >> 1);
            unsigned i1 = (j1 & 1) ? ((pA >> 8) & 0xffu) : (pA & 0xffu);
            unsigned pB = __shfl_sync(FULLM, pk, j2 >> 1);
            unsigned i2 = (j2 & 1) ? ((pB >> 8) & 0xffu) : (pB & 0xffu);
            float* o = out + (size_t)rowA * 48;
            o[lane] = xA[(int)i1 * 3 + c1];
            if (lane < 16)
                o[32 + lane] = xA[(int)i2 * 3 + c2];
        }
        // ---- epilogue row B ----
        if (hasB) {
            unsigned pA = __shfl_sync(FULLM, pk, 8 + (j1 >> 1));
            unsigned i1 = (j1 & 1) ? ((pA >> 8) & 0xffu) : (pA & 0xffu);
            unsigned pB = __shfl_sync(FULLM, pk, 8 + (j2 >> 1));
            unsigned i2 = (j2 & 1) ? ((pB >> 8) & 0xffu) : (pB & 0xffu);
            float* o = out + (size_t)(rowA + 1) * 48;
            o[lane] = xB[(int)i1 * 3 + c1];
            if (lane < 16)
                o[32 + lane] = xB[(int)i2 * 3 + c2];
        }
    }
}

extern "C" void kernel_launch(void* const* d_in, const int* in_sizes, int n_in,
                              void* d_out, int out_size)
{
    const float* x   = (const float*)d_in[0];
    float*       out = (float*)d_out;
    int nrows = in_sizes[0] / 192;
    int rowsPerBlock = WPB * RPW;
    int grid = (nrows + rowsPerBlock - 1) / rowsPerBlock;
    vecnorm_topk_kernel<<<grid, WPB * 32>>>(x, out, nrows);
}

// round 15
// speedup vs baseline: 1.2782x; 1.0637x over previous
#include <cuda_runtime.h>

// VectorNormSelection, round 15: R14 + fused pair epilogue + RPW 8.
// Network/detector/slow-path identical to R14 (validated):
//   - packed u32 keys (norm&~63)|(63-idx), per-row sort-16 phase,
//     two-row shared merge phases (B rides in lanes 8-15/24-31),
//     A top-16 sorted in lanes 0-7, B in lanes 8-15
//   - exactness detector per row; rare rows rerun exact u64 network
// New: the pair's 96 output floats are emitted as 3 dense groups
// (f = 32m + lane): one precomputed packed routing constant per group gives
// src pk-lane, idx byte-shift, and row-base offset -> 1 SHFL + 1 gather load
// + 1 fully-coalesced store per group, no divergent half-warp tails.
// RPW=8 amortizes the warp prologue over 8 rows.

#define WPB 8          // warps per block
#define RPW 8          // rows per warp (processed in pairs)
#define FULLM 0xffffffffu

typedef unsigned u32;
typedef unsigned long long u64;

// ---------- packed u32 stages (R12/R14 primitives) ----------
template <int JH>
__device__ __forceinline__ void pstage_x(u32& e0, u32& e1, bool takeMax) {
    u32 p0 = __shfl_xor_sync(FULLM, e0, JH);
    u32 p1 = __shfl_xor_sync(FULLM, e1, JH);
    e0 = takeMax ? max(e0, p0) : min(e0, p0);
    e1 = takeMax ? max(e1, p1) : min(e1, p1);
}
__device__ __forceinline__ void pstage_l(u32& e0, u32& e1, bool descR) {
    u32 hi = max(e0, e1), lo = min(e0, e1);
    e0 = descR ? hi : lo;
    e1 = descR ? lo : hi;
}
__device__ __forceinline__ void pstage_lT(u32& e0, u32& e1) {
    u32 hi = max(e0, e1), lo = min(e0, e1);
    e0 = hi; e1 = lo;
}
template <int XM>
__device__ __forceinline__ void phalve_x(u32& e0, u32& e1) {
    u32 p0 = __shfl_xor_sync(FULLM, e0, XM);
    u32 p1 = __shfl_xor_sync(FULLM, e1, XM);
    e0 = max(e0, p1);
    e1 = max(e1, p0);
}

struct Dirs {
    bool d2, d4, d8, x1_d4, x2_d8, x1_d8, x4_T, x2_T, x1_T;
};

__device__ __forceinline__ void psort16(u32& k0, u32& k1, const Dirs& D) {
    pstage_l(k0, k1, D.d2);          // k=2  j=1
    pstage_x<1>(k0, k1, D.x1_d4);    // k=4  j=2
    pstage_l(k0, k1, D.d4);          //      j=1
    pstage_x<2>(k0, k1, D.x2_d8);    // k=8  j=4
    pstage_x<1>(k0, k1, D.x1_d8);    //      j=2
    pstage_l(k0, k1, D.d8);          //      j=1
    pstage_x<4>(k0, k1, D.x4_T);     // k=16 j=8
    pstage_x<2>(k0, k1, D.x2_T);     //      j=4
    pstage_x<1>(k0, k1, D.x1_T);     //      j=2
    pstage_lT(k0, k1);               //      j=1 (desc)
}
__device__ __forceinline__ void pclean(u32& k0, u32& k1, const Dirs& D) {
    pstage_x<4>(k0, k1, D.x4_T);
    pstage_x<2>(k0, k1, D.x2_T);
    pstage_x<1>(k0, k1, D.x1_T);
    pstage_lT(k0, k1);
}

// ---------- exact u64 network (slow path; R7-validated) ----------
__device__ __forceinline__ u64 cexg(u64 e, u64 p, bool takeMax) {
    return ((p > e) == takeMax) ? p : e;
}
template <int JH>
__device__ __forceinline__ void kstage_x(u64& e0, u64& e1, bool takeMax) {
    u64 p0 = __shfl_xor_sync(FULLM, e0, JH);
    u64 p1 = __shfl_xor_sync(FULLM, e1, JH);
    e0 = cexg(e0, p0, takeMax);
    e1 = cexg(e1, p1, takeMax);
}
__device__ __forceinline__ void kstage_l(u64& e0, u64& e1, bool descR) {
    bool gt = e0 > e1;
    u64 hi = gt ? e0 : e1;
    u64 lo = gt ? e1 : e0;
    e0 = descR ? hi : lo;
    e1 = descR ? lo : hi;
}
template <int XM>
__device__ __forceinline__ void khalve_x(u64& e0, u64& e1) {
    u64 p0 = __shfl_xor_sync(FULLM, e0, XM);
    u64 p1 = __shfl_xor_sync(FULLM, e1, XM);
    e0 = (p1 > e0) ? p1 : e0;
    e1 = (p0 > e1) ? p0 : e1;
}
__device__ __noinline__ unsigned kexact(u32 w0, u32 w1, u32 tag0, u32 tag1, const Dirs& D) {
    u64 e0 = ((u64)w0 << 32) | (u64)tag0;
    u64 e1 = ((u64)w1 << 32) | (u64)tag1;
    kstage_l(e0, e1, D.d2);
    kstage_x<1>(e0, e1, D.x1_d4);
    kstage_l(e0, e1, D.d4);
    kstage_x<2>(e0, e1, D.x2_d8);
    kstage_x<1>(e0, e1, D.x1_d8);
    kstage_l(e0, e1, D.d8);
    kstage_x<4>(e0, e1, D.x4_T);
    kstage_x<2>(e0, e1, D.x2_T);
    kstage_x<1>(e0, e1, D.x1_T);
    kstage_l(e0, e1, true);
    khalve_x<15>(e0, e1);
    kstage_x<4>(e0, e1, D.x4_T);
    kstage_x<2>(e0, e1, D.x2_T);
    kstage_x<1>(e0, e1, D.x1_T);
    kstage_l(e0, e1, true);
    khalve_x<23>(e0, e1);
    kstage_x<4>(e0, e1, D.x4_T);
    kstage_x<2>(e0, e1, D.x2_T);
    kstage_x<1>(e0, e1, D.x1_T);
    kstage_l(e0, e1, true);
    unsigned idx0 = 63u - (unsigned)(e0 & 63ull);
    unsigned idx1 = 63u - (unsigned)(e1 & 63ull);
    return idx0 | (idx1 << 8);
}

__global__ void __launch_bounds__(WPB * 32)
vecnorm_topk_kernel(const float* __restrict__ x, float* __restrict__ out, int nrows)
{
    const int lane = threadIdx.x & 31;
    const int wg   = blockIdx.x * WPB + (threadIdx.x >> 5);
    const int rowBase = wg * RPW;
    if (rowBase >= nrows) return;
    const int rowsHere = min(RPW, nrows - rowBase);

    Dirs D;
    D.d2 = ((lane & 1) == 0);
    D.d4 = ((lane & 2) == 0);
    D.d8 = ((lane & 4) == 0);
    D.x1_d4 = (D.d2 == D.d4);
    D.x2_d8 = (D.d4 == D.d8);
    D.x1_d8 = (D.d2 == D.d8);
    D.x4_T  = D.d8;
    D.x2_T  = D.d4;
    D.x1_T  = D.d2;

    const u32 tag0 = (u32)(63 - 2 * lane);
    const u32 tag1 = (u32)(62 - 2 * lane);

    // ---- fused-epilogue routing constants (per pair-group m = 0,1,2) ----
    // f = 32m + lane in [0,96): row = f>=48 ? B : A, g = f mod 48,
    // rank j = g/3, comp c = g%3. Packed:
    //   bits [0:5)   src pk-lane  (row==B ? 8 : 0) + (j>>1)
    //   bits [8:16)  idx byte shift = (j&1)*8
    //   bits [16:26) row offset + comp = (row==B)*192 + c
    //   bit  30      row==B (store needs hasB)
    u32 ep[3];
#pragma unroll
    for (int m = 0; m < 3; m++) {
        int f  = 32 * m + lane;
        int rs = (f >= 48) ? 1 : 0;
        int g  = f - 48 * rs;
        int j  = g / 3;
        int c  = g - 3 * j;
        ep[m] = (u32)((8 * rs + (j >> 1)) | (((j & 1) * 8) << 8) |
                      ((rs * 192 + c) << 16) | (rs << 30));
    }

#pragma unroll 1
    for (int i = 0; i < rowsHere; i += 2) {
        const int rowA = rowBase + i;
        const bool hasB = (i + 1) < rowsHere;
        const float* xA = x + (size_t)rowA * 192;
        const float* xB = hasB ? (xA + 192) : xA;

        // ---- load + norms for both rows ----
        const float2* a2 = reinterpret_cast<const float2*>(xA);
        float2 aa = a2[3 * lane + 0];
        float2 ab = a2[3 * lane + 1];
        float2 ac = a2[3 * lane + 2];
        float nA0 = fmaf(aa.x, aa.x, fmaf(aa.y, aa.y, ab.x * ab.x));
        float nA1 = fmaf(ab.y, ab.y, fmaf(ac.x, ac.x, ac.y * ac.y));
        const float2* b2 = reinterpret_cast<const float2*>(xB);
        float2 ba = b2[3 * lane + 0];
        float2 bb = b2[3 * lane + 1];
        float2 bc = b2[3 * lane + 2];
        float nB0 = fmaf(ba.x, ba.x, fmaf(ba.y, ba.y, bb.x * bb.x));
        float nB1 = fmaf(bb.y, bb.y, fmaf(bc.x, bc.x, bc.y * bc.y));

        u32 wA0 = __float_as_uint(nA0), wA1 = __float_as_uint(nA1);
        u32 wB0 = __float_as_uint(nB0), wB1 = __float_as_uint(nB1);

        // ---- packed keys + per-row sort-16 phase ----
        u32 kA0 = (wA0 & 0xFFFFFFC0u) | tag0;
        u32 kA1 = (wA1 & 0xFFFFFFC0u) | tag1;
        u32 kB0 = (wB0 & 0xFFFFFFC0u) | tag0;
        u32 kB1 = (wB1 & 0xFFFFFFC0u) | tag1;
        psort16(kA0, kA1, D);
        psort16(kB0, kB1, D);

        // ---- per-row halvings; upper halves adopt row B's mirrored tops ----
        phalve_x<15>(kA0, kA1);
        phalve_x<15>(kB0, kB1);
        if (lane & 8) { kA0 = kB0; kA1 = kB1; }   // lanes 8-15 & 24-31 carry B

        // ---- shared merge-A clean, shared merge B ----
        pclean(kA0, kA1, D);        // 0-7:A(g01) 8-15:B(g01) 16-23:A(g23) 24-31:B(g23)
        phalve_x<23>(kA0, kA1);     // A: 0-7 vs 16-23 ; B: 8-15 vs 24-31
        pclean(kA0, kA1, D);        // A top16 sorted in lanes 0-7; B in 8-15

        // ---- exactness detector, per row (R12/R14-validated) ----
        u32 v0t = kA0 >> 6, v1t = kA1 >> 6;
        u32 nv0 = __shfl_down_sync(FULLM, v0t, 1);
        bool adj = (lane < 16) && ((v0t == v1t) || (((lane & 7) < 7) && (v1t == nv0)));
        u32 adjm = __ballot_sync(FULLM, adj);
        u32 t26A = __shfl_sync(FULLM, v1t, 7);
        u32 t26B = __shfl_sync(FULLM, v1t, 15);
        int totA = __popc(__ballot_sync(FULLM, (wA0 >> 6) == t26A)) +
                   __popc(__ballot_sync(FULLM, (wA1 >> 6) == t26A));
        int totB = __popc(__ballot_sync(FULLM, (wB0 >> 6) == t26B)) +
                   __popc(__ballot_sync(FULLM, (wB1 >> 6) == t26B));
        bool slowA = ((adjm & 0x00FFu) != 0) || (totA >= 2);
        bool slowB = hasB && (((adjm & 0xFF00u) != 0) || (totB >= 2));

        // ---- per-lane pk (A valid in lanes 0-7, B in lanes 8-15) ----
        unsigned pk = (63u - (kA0 & 63u)) | ((63u - (kA1 & 63u)) << 8);
        if (slowA) {
            unsigned pkx = kexact(wA0, wA1, tag0, tag1, D);
            if (lane < 8) pk = pkx;
        }
        if (slowB) {
            unsigned pkx = kexact(wB0, wB1, tag0, tag1, D);
            unsigned up = __shfl_sync(FULLM, pkx, lane & 7);
            if (lane >= 8 && lane < 16) pk = up;
        }

        // ---- fused pair epilogue: 96 floats as 3 dense groups ----
        float* oP = out + (size_t)rowA * 48;
#pragma unroll
        for (int m = 0; m < 3; m++) {
            u32 p = ep[m];
            unsigned pkv = __shfl_sync(FULLM, pk, (int)(p & 31u));
            unsigned idx = (pkv >> ((p >> 8) & 31u)) & 0xffu;
            float v = xA[((p >> 16) & 0x3ffu) + 3 * (int)idx];
            if (hasB || !(p & (1u << 30)))
                oP[32 * m + lane] = v;
        }
    }
}

extern "C" void kernel_launch(void* const* d_in, const int* in_sizes, int n_in,
                              void* d_out, int out_size)
{
    const float* x   = (const float*)d_in[0];
    float*       out = (float*)d_out;
    int nrows = in_sizes[0] / 192;
    int rowsPerBlock = WPB * RPW;
    int grid = (nrows + rowsPerBlock - 1) / rowsPerBlock;
    vecnorm_topk_kernel<<<grid, WPB * 32>>>(x, out, nrows);
}